// round 6
// baseline (speedup 1.0000x reference)
#include <cuda_runtime.h>
#include <math.h>
#include <stdint.h>

// Problem constants
#define Bb 4
#define Hh 8
#define BHn 32
#define NN 2048
#define Dd 512
#define DHd 64
#define MF 256
#define CK 128
#define NC 16

// Scratch
__device__ float g_qp[(size_t)BHn * NN * MF];          // exp'd q features
__device__ float g_kp[(size_t)BHn * NN * MF];          // RAW dd - diag (exp at consumers)
__device__ float g_S [(size_t)BHn * NC * MF * DHd];
__device__ float g_z [BHn * NC * MF];
__device__ float g_kmax[BHn];

__device__ __forceinline__ float tf32r(float x) {
    uint32_t u = __float_as_uint(x);
    u = (u + 0x1000u) & 0xFFFFE000u;
    return __uint_as_float(u);
}
__device__ __forceinline__ uint32_t tf32u(float x) {
    return (__float_as_uint(x) + 0x1000u) & 0xFFFFE000u;
}
__device__ __forceinline__ float kfeat(float v, float m) {
    return 0.0625f * (__expf(v - m) + 1e-4f);
}

// Warp-level tf32 MMA
__device__ __forceinline__ void mma16n8k8(float c[4], const uint32_t a[4],
                                          const uint32_t b[2]) {
    asm volatile(
        "mma.sync.aligned.m16n8k8.row.col.f32.tf32.tf32.f32 "
        "{%0,%1,%2,%3}, {%4,%5,%6,%7}, {%8,%9}, {%0,%1,%2,%3};"
        : "+f"(c[0]), "+f"(c[1]), "+f"(c[2]), "+f"(c[3])
        : "r"(a[0]), "r"(a[1]), "r"(a[2]), "r"(a[3]), "r"(b[0]), "r"(b[1]));
}

// ---------------------------------------------------------------------------
// Feature-map kernel (split-tf32 tensor core; __expf; inits g_kmax in Q pass)
// ---------------------------------------------------------------------------
template <bool IS_Q>
__global__ void __launch_bounds__(256) feat_kernel(const float* __restrict__ xin,
                                                   const float* __restrict__ proj) {
    __shared__ uint4 ps[1024];
    __shared__ float mx[64][2];
    __shared__ float bred[8];

    const int t = threadIdx.x, wid = t >> 5, lane = t & 31;
    const int g = lane >> 2, tq = lane & 3;
    const int wm = wid >> 1, wn = wid & 1;
    const int bh = blockIdx.y, b = bh >> 3, h = bh & 7;
    const int n0 = blockIdx.x * 64;
    const int r0 = n0 + wm * 16;

    if (IS_Q && blockIdx.x == 0 && t == 0) g_kmax[bh] = -1e30f;

    uint4 ah[8], al[8];
    float ss0 = 0.f, ss1 = 0.f;
    const float* xb = xin + ((size_t)b * NN + r0) * Dd + h * DHd;
#pragma unroll
    for (int ks = 0; ks < 8; ks++) {
        float x0 = xb[(size_t)g * Dd + ks * 8 + tq];
        float x1 = xb[(size_t)(g + 8) * Dd + ks * 8 + tq];
        float x2 = xb[(size_t)g * Dd + ks * 8 + tq + 4];
        float x3 = xb[(size_t)(g + 8) * Dd + ks * 8 + tq + 4];
        ss0 += x0 * x0 + x2 * x2;
        ss1 += x1 * x1 + x3 * x3;
        uint32_t h0 = __float_as_uint(x0) & 0xFFFFE000u;
        uint32_t h1 = __float_as_uint(x1) & 0xFFFFE000u;
        uint32_t h2 = __float_as_uint(x2) & 0xFFFFE000u;
        uint32_t h3 = __float_as_uint(x3) & 0xFFFFE000u;
        ah[ks] = make_uint4(h0, h1, h2, h3);
        al[ks] = make_uint4(__float_as_uint(x0 - __uint_as_float(h0)),
                            __float_as_uint(x1 - __uint_as_float(h1)),
                            __float_as_uint(x2 - __uint_as_float(h2)),
                            __float_as_uint(x3 - __uint_as_float(h3)));
    }
    ss0 += __shfl_xor_sync(0xffffffffu, ss0, 1);
    ss0 += __shfl_xor_sync(0xffffffffu, ss0, 2);
    ss1 += __shfl_xor_sync(0xffffffffu, ss1, 1);
    ss1 += __shfl_xor_sync(0xffffffffu, ss1, 2);
    const float diag0 = ss0 * 0.0625f, diag1 = ss1 * 0.0625f;

    float acc[16][4];
#pragma unroll
    for (int i = 0; i < 16; i++)
#pragma unroll
        for (int j = 0; j < 4; j++) acc[i][j] = 0.f;

    for (int ks = 0; ks < 8; ks++) {
        __syncthreads();
#pragma unroll
        for (int it = 0; it < 4; it++) {
            int slot = it * 256 + t;
            int nt = slot >> 5, sl = slot & 31;
            int sg = sl >> 2, stq = sl & 3;
            const float* pp = proj + (nt * 8 + sg) * 64 + ks * 8 + stq;
            float p0 = pp[0], p1 = pp[4];
            uint32_t h0 = __float_as_uint(p0) & 0xFFFFE000u;
            uint32_t h1 = __float_as_uint(p1) & 0xFFFFE000u;
            ps[slot] = make_uint4(h0, h1,
                                  __float_as_uint(p0 - __uint_as_float(h0)),
                                  __float_as_uint(p1 - __uint_as_float(h1)));
        }
        __syncthreads();
#pragma unroll
        for (int ntl = 0; ntl < 16; ntl++) {
            uint4 pv = ps[(wn * 16 + ntl) * 32 + lane];
            uint32_t bhi[2] = {pv.x, pv.y};
            uint32_t blo[2] = {pv.z, pv.w};
            mma16n8k8(acc[ntl], (const uint32_t*)&ah[ks], bhi);
            mma16n8k8(acc[ntl], (const uint32_t*)&al[ks], bhi);
            mma16n8k8(acc[ntl], (const uint32_t*)&ah[ks], blo);
        }
    }

    const float normalizer = 0.35355339059327373f;
#pragma unroll
    for (int ntl = 0; ntl < 16; ntl++)
#pragma unroll
        for (int j = 0; j < 4; j++) acc[ntl][j] *= normalizer;

    if (IS_Q) {
        float m0 = -1e30f, m1 = -1e30f;
#pragma unroll
        for (int ntl = 0; ntl < 16; ntl++) {
            m0 = fmaxf(m0, fmaxf(acc[ntl][0], acc[ntl][1]));
            m1 = fmaxf(m1, fmaxf(acc[ntl][2], acc[ntl][3]));
        }
        m0 = fmaxf(m0, __shfl_xor_sync(0xffffffffu, m0, 1));
        m0 = fmaxf(m0, __shfl_xor_sync(0xffffffffu, m0, 2));
        m1 = fmaxf(m1, __shfl_xor_sync(0xffffffffu, m1, 1));
        m1 = fmaxf(m1, __shfl_xor_sync(0xffffffffu, m1, 2));
        if (tq == 0) {
            mx[wm * 16 + g][wn] = m0;
            mx[wm * 16 + g + 8][wn] = m1;
        }
        __syncthreads();
        const float M0 = fmaxf(mx[wm * 16 + g][0], mx[wm * 16 + g][1]);
        const float M1 = fmaxf(mx[wm * 16 + g + 8][0], mx[wm * 16 + g + 8][1]);
        float* o0 = g_qp + ((size_t)bh * NN + r0 + g) * MF + wn * 128;
        float* o1 = g_qp + ((size_t)bh * NN + r0 + g + 8) * MF + wn * 128;
#pragma unroll
        for (int ntl = 0; ntl < 16; ntl++) {
            float2 v0, v1;
            v0.x = 0.0625f * (__expf(acc[ntl][0] - diag0 - M0) + 1e-4f);
            v0.y = 0.0625f * (__expf(acc[ntl][1] - diag0 - M0) + 1e-4f);
            v1.x = 0.0625f * (__expf(acc[ntl][2] - diag1 - M1) + 1e-4f);
            v1.y = 0.0625f * (__expf(acc[ntl][3] - diag1 - M1) + 1e-4f);
            *(float2*)(o0 + ntl * 8 + tq * 2) = v0;
            *(float2*)(o1 + ntl * 8 + tq * 2) = v1;
        }
    } else {
        float km = -1e30f;
        float* o0 = g_kp + ((size_t)bh * NN + r0 + g) * MF + wn * 128;
        float* o1 = g_kp + ((size_t)bh * NN + r0 + g + 8) * MF + wn * 128;
#pragma unroll
        for (int ntl = 0; ntl < 16; ntl++) {
            km = fmaxf(km, fmaxf(fmaxf(acc[ntl][0], acc[ntl][1]),
                                 fmaxf(acc[ntl][2], acc[ntl][3])));
            float2 v0 = make_float2(acc[ntl][0] - diag0, acc[ntl][1] - diag0);
            float2 v1 = make_float2(acc[ntl][2] - diag1, acc[ntl][3] - diag1);
            *(float2*)(o0 + ntl * 8 + tq * 2) = v0;
            *(float2*)(o1 + ntl * 8 + tq * 2) = v1;
        }
#pragma unroll
        for (int off = 16; off; off >>= 1)
            km = fmaxf(km, __shfl_xor_sync(0xffffffffu, km, off));
        if (lane == 0) bred[wid] = km;
        __syncthreads();
        if (t == 0) {
            float m = bred[0];
            for (int w = 1; w < 8; w++) m = fmaxf(m, bred[w]);
            int* addr = (int*)&g_kmax[bh];
            int old = *addr;
            while (__int_as_float(old) < m) {
                int assumed = old;
                old = atomicCAS(addr, assumed, __float_as_int(m));
                if (old == assumed) break;
            }
        }
    }
}

// ---------------------------------------------------------------------------
// Per-chunk local KV state; exp applied on the fly (g_kp holds raw dd-diag).
// ---------------------------------------------------------------------------
__global__ void __launch_bounds__(256) chunk_kv_kernel(const float* __restrict__ vin) {
    const int t = threadIdx.x, wid = t >> 5, lane = t & 31;
    const int g = lane >> 2, tq = lane & 3;
    const int c = blockIdx.x, bh = blockIdx.y;
    const int b = bh >> 3, h = bh & 7;
    const int n0 = c * CK;
    const float* kb = g_kp + (size_t)(bh * NN + n0) * MF;
    const float* vb = vin + ((size_t)(b * NN + n0)) * Dd + h * DHd;
    const float m = g_kmax[bh];

    float acc[2][8][4];
#pragma unroll
    for (int i = 0; i < 2; i++)
#pragma unroll
        for (int n = 0; n < 8; n++)
#pragma unroll
            for (int j = 0; j < 4; j++) acc[i][n][j] = 0.f;
    float z0[2] = {0.f, 0.f}, z1[2] = {0.f, 0.f};

    for (int tk = 0; tk < 16; tk++) {
        const int j0 = tk * 8 + tq, j1 = j0 + 4;
        uint32_t af[2][4];
#pragma unroll
        for (int i = 0; i < 2; i++) {
            int mm = (wid * 2 + i) * 16 + g;
            float a0 = kfeat(kb[(size_t)j0 * MF + mm], m);
            float a1 = kfeat(kb[(size_t)j0 * MF + mm + 8], m);
            float a2 = kfeat(kb[(size_t)j1 * MF + mm], m);
            float a3 = kfeat(kb[(size_t)j1 * MF + mm + 8], m);
            z0[i] += a0 + a2;
            z1[i] += a1 + a3;
            af[i][0] = tf32u(a0); af[i][1] = tf32u(a1);
            af[i][2] = tf32u(a2); af[i][3] = tf32u(a3);
        }
#pragma unroll
        for (int nt = 0; nt < 8; nt++) {
            uint32_t bf[2];
            bf[0] = tf32u(vb[(size_t)j0 * Dd + nt * 8 + g]);
            bf[1] = tf32u(vb[(size_t)j1 * Dd + nt * 8 + g]);
            mma16n8k8(acc[0][nt], af[0], bf);
            mma16n8k8(acc[1][nt], af[1], bf);
        }
    }

#pragma unroll
    for (int i = 0; i < 2; i++) {
        z0[i] += __shfl_xor_sync(0xffffffffu, z0[i], 1);
        z0[i] += __shfl_xor_sync(0xffffffffu, z0[i], 2);
        z1[i] += __shfl_xor_sync(0xffffffffu, z1[i], 1);
        z1[i] += __shfl_xor_sync(0xffffffffu, z1[i], 2);
    }
    if (tq == 0) {
        float* zp = g_z + (bh * NC + c) * MF;
#pragma unroll
        for (int i = 0; i < 2; i++) {
            int mm = (wid * 2 + i) * 16 + g;
            zp[mm] = z0[i];
            zp[mm + 8] = z1[i];
        }
    }

    float* Sp = g_S + (size_t)(bh * NC + c) * MF * DHd;
#pragma unroll
    for (int i = 0; i < 2; i++) {
        int mm = (wid * 2 + i) * 16 + g;
#pragma unroll
        for (int nt = 0; nt < 8; nt++) {
            *(float2*)(Sp + (size_t)mm * DHd + nt * 8 + tq * 2) =
                make_float2(acc[i][nt][0], acc[i][nt][1]);
            *(float2*)(Sp + (size_t)(mm + 8) * DHd + nt * 8 + tq * 2) =
                make_float2(acc[i][nt][2], acc[i][nt][3]);
        }
    }
}

// ---------------------------------------------------------------------------
// Fully parallel exclusive prefix
// ---------------------------------------------------------------------------
__global__ void __launch_bounds__(256) prefix_kernel() {
    const int blk = blockIdx.x;
    if (blk < 2048) {
        int idx = blk * 256 + threadIdx.x;
        int bh = idx >> 14;
        int me = idx & 16383;
        float* base = g_S + (size_t)bh * (NC * MF * DHd) + me;
        float run = 0.f;
#pragma unroll
        for (int c = 0; c < NC; c++) {
            float v = base[(size_t)c * (MF * DHd)];
            base[(size_t)c * (MF * DHd)] = run;
            run += v;
        }
    } else {
        int bh = blk - 2048;
        int mm = threadIdx.x;
        float* zb = g_z + bh * NC * MF + mm;
        float run = 0.f;
#pragma unroll
        for (int c = 0; c < NC; c++) {
            float v = zb[c * MF];
            zb[c * MF] = run;
            run += v;
        }
    }
}

// ---------------------------------------------------------------------------
// Output kernel: fragment-native smem, 2 CTAs/SM, exp-on-staging for K.
// fragQ: Q half as A-frags (4mt x 16kt, 32KB), later masked-A frags.
// fragB0: K chunk as B-frags (8ks x ntb, 32KB max).
// fragB1: S half / V as B-frags (16kt x 8nt, 32KB).
// ---------------------------------------------------------------------------
#define OUT_DSMEM (3 * 32768)

__global__ void __launch_bounds__(256, 2) out_kernel(const float* __restrict__ vin,
                                                     float* __restrict__ outp) {
    extern __shared__ char smraw[];
    uint4* fragQ = (uint4*)smraw;
    uint2* fragB0 = (uint2*)(smraw + 32768);
    uint2* fragB1 = (uint2*)(smraw + 65536);
    __shared__ float den4[256];
    __shared__ float den[64];
    __shared__ float dinv[64];

    const int t = threadIdx.x, wid = t >> 5, lane = t & 31;
    const int g = lane >> 2, tq = lane & 3;
    const int wm = wid >> 2, wn = wid & 3;
    const int c = blockIdx.x, bh = blockIdx.y, hp = blockIdx.z;
    const int b = bh >> 3, h = bh & 7;
    const int n0 = c * CK;
    const int r0c = hp * 64;
    const int NT1 = hp ? 4 : 2;         // phase-1 B ntiles per warp
    const int ntb = hp ? 16 : 8;        // phase-1 B ntiles total
    const int sft = hp ? 4 : 3;
    const int NJT = hp ? 16 : 8;        // phase-3 ktiles

    const float* qbase = g_qp + (size_t)(bh * NN + n0 + r0c) * MF;
    const float* kbase = g_kp + (size_t)(bh * NN + n0) * MF;
    const float* Sbase = g_S + (size_t)(bh * NC + c) * MF * DHd;
    const float* zg = g_z + (bh * NC + c) * MF;
    const float kmaxv = g_kmax[bh];

    // den partial: q . (z_prev + 1e-6)
    {
        int i = t >> 2, qq = t & 3;
        float s = 0.f;
        const float* qr = qbase + (size_t)i * MF + qq * 64;
        const float* zr = zg + qq * 64;
#pragma unroll 4
        for (int mm = 0; mm < 64; mm += 4) {
            float4 q4 = *(const float4*)(qr + mm);
            s += q4.x * (zr[mm + 0] + 1e-6f) + q4.y * (zr[mm + 1] + 1e-6f)
               + q4.z * (zr[mm + 2] + 1e-6f) + q4.w * (zr[mm + 3] + 1e-6f);
        }
        den4[t] = s;
    }

    float accA[2][4][4];
#pragma unroll
    for (int i = 0; i < 2; i++)
#pragma unroll
        for (int j = 0; j < 4; j++)
#pragma unroll
            for (int s = 0; s < 4; s++) accA[i][j][s] = 0.f;
    float acc2[2][2][4];
#pragma unroll
    for (int i = 0; i < 2; i++)
#pragma unroll
        for (int j = 0; j < 2; j++)
#pragma unroll
            for (int s = 0; s < 4; s++) acc2[i][j][s] = 0.f;

#pragma unroll 1
    for (int hf = 0; hf < 2; hf++) {
        if (hf) __syncthreads();
        // Stage Q half hf as A-frags: 64 tiles (4mt x 16kt), 8 per warp
#pragma unroll
        for (int i = 0; i < 8; i++) {
            int tile = i * 8 + wid;
            int tm = tile >> 4, tk = tile & 15;
            const float* qp = qbase + (size_t)(tm * 16 + g) * MF + hf * 128 + tk * 8 + tq;
            fragQ[tile * 32 + lane] =
                make_uint4(tf32u(qp[0]), tf32u(qp[8 * MF]),
                           tf32u(qp[4]), tf32u(qp[8 * MF + 4]));
        }
        // Stage K chunk kc=2hf as B-frags (exp applied)
        for (int i = 0; i < ntb; i++) {  // 8ks*ntb/8 warps = ntb per warp
            int tile = i * 8 + wid;
            int ks = tile >> sft, tn = tile & (ntb - 1);
            const float* kp = kbase + (size_t)(tn * 8 + g) * MF + (2 * hf) * 64 + ks * 8 + tq;
            fragB0[tile * 32 + lane] =
                make_uint2(tf32u(kfeat(kp[0], kmaxv)), tf32u(kfeat(kp[4], kmaxv)));
        }
        // Stage S half hf as B-frags: 128 tiles (16ks x 8nt), 16 per warp
#pragma unroll
        for (int i = 0; i < 16; i++) {
            int tile = i * 8 + wid;
            int ks = tile >> 3, tn = tile & 7;
            const float* sp = Sbase + (size_t)(hf * 128 + ks * 8 + tq) * DHd + tn * 8 + g;
            fragB1[tile * 32 + lane] = make_uint2(tf32u(sp[0]), tf32u(sp[4 * DHd]));
        }
        __syncthreads();
        if (hf == 0 && t < 64)
            den[t] = den4[4 * t] + den4[4 * t + 1] + den4[4 * t + 2] + den4[4 * t + 3];

        // Phase 1 (kc=2hf): Q ktiles 0..7
#pragma unroll
        for (int ks = 0; ks < 8; ks++) {
            uint4 af[2];
#pragma unroll
            for (int mt = 0; mt < 2; mt++)
                af[mt] = fragQ[((wm * 2 + mt) * 16 + ks) * 32 + lane];
#pragma unroll
            for (int nt = 0; nt < 4; nt++) {
                if (nt >= NT1) break;
                uint2 bf = fragB0[(ks * ntb + wn * NT1 + nt) * 32 + lane];
                mma16n8k8(accA[0][nt], (const uint32_t*)&af[0], (const uint32_t*)&bf);
                mma16n8k8(accA[1][nt], (const uint32_t*)&af[1], (const uint32_t*)&bf);
            }
        }
        // Phase 2 (S half hf): Q ktiles 0..15
#pragma unroll 2
        for (int ks = 0; ks < 16; ks++) {
            uint4 af[2];
#pragma unroll
            for (int mt = 0; mt < 2; mt++)
                af[mt] = fragQ[((wm * 2 + mt) * 16 + ks) * 32 + lane];
#pragma unroll
            for (int nt = 0; nt < 2; nt++) {
                uint2 bf = fragB1[(ks * 8 + wn * 2 + nt) * 32 + lane];
                mma16n8k8(acc2[0][nt], (const uint32_t*)&af[0], (const uint32_t*)&bf);
                mma16n8k8(acc2[1][nt], (const uint32_t*)&af[1], (const uint32_t*)&bf);
            }
        }
        __syncthreads();
        // Stage K chunk kc=2hf+1
        for (int i = 0; i < ntb; i++) {
            int tile = i * 8 + wid;
            int ks = tile >> sft, tn = tile & (ntb - 1);
            const float* kp = kbase + (size_t)(tn * 8 + g) * MF + (2 * hf + 1) * 64 + ks * 8 + tq;
            fragB0[tile * 32 + lane] =
                make_uint2(tf32u(kfeat(kp[0], kmaxv)), tf32u(kfeat(kp[4], kmaxv)));
        }
        __syncthreads();
        // Phase 1 (kc=2hf+1): Q ktiles 8..15
#pragma unroll
        for (int ks = 0; ks < 8; ks++) {
            uint4 af[2];
#pragma unroll
            for (int mt = 0; mt < 2; mt++)
                af[mt] = fragQ[((wm * 2 + mt) * 16 + 8 + ks) * 32 + lane];
#pragma unroll
            for (int nt = 0; nt < 4; nt++) {
                if (nt >= NT1) break;
                uint2 bf = fragB0[(ks * ntb + wn * NT1 + nt) * 32 + lane];
                mma16n8k8(accA[0][nt], (const uint32_t*)&af[0], (const uint32_t*)&bf);
                mma16n8k8(accA[1][nt], (const uint32_t*)&af[1], (const uint32_t*)&bf);
            }
        }
    }

    // ---- Mask tril + rowsum -> den ----
#pragma unroll
    for (int mt = 0; mt < 2; mt++) {
        int i0 = wm * 32 + mt * 16 + g;
        int lim0 = r0c + i0, lim1 = lim0 + 8;
        float rs0 = 0.f, rs1 = 0.f;
#pragma unroll
        for (int nt = 0; nt < 4; nt++) {
            if (nt >= NT1) break;
            int cb = (wn * NT1 + nt) * 8 + tq * 2;
            float v0 = (cb     <= lim0) ? accA[mt][nt][0] : 0.f;
            float v1 = (cb + 1 <= lim0) ? accA[mt][nt][1] : 0.f;
            float v2 = (cb     <= lim1) ? accA[mt][nt][2] : 0.f;
            float v3 = (cb + 1 <= lim1) ? accA[mt][nt][3] : 0.f;
            accA[mt][nt][0] = v0; accA[mt][nt][1] = v1;
            accA[mt][nt][2] = v2; accA[mt][nt][3] = v3;
            rs0 += v0 + v1;
            rs1 += v2 + v3;
        }
        rs0 += __shfl_xor_sync(0xffffffffu, rs0, 1);
        rs0 += __shfl_xor_sync(0xffffffffu, rs0, 2);
        rs1 += __shfl_xor_sync(0xffffffffu, rs1, 1);
        rs1 += __shfl_xor_sync(0xffffffffu, rs1, 2);
        if (tq == 0) {
            atomicAdd(&den[i0], rs0);
            atomicAdd(&den[i0 + 8], rs1);
        }
    }
    __syncthreads();   // all MMA + den atomics done; fragQ/fragB1 free

    // ---- dinv; masked-A frags into fragQ; V frags into fragB1 ----
    if (t < 64) dinv[t] = 1.0f / den[t];
    {
        int l0 = g * 4 + ((2 * tq) & 3);
        int s0 = 2 * ((2 * tq) >> 2);
        int l1 = g * 4 + ((2 * tq + 1) & 3);
        int s1 = 2 * ((2 * tq + 1) >> 2);
#pragma unroll
        for (int mt = 0; mt < 2; mt++)
#pragma unroll
            for (int nt = 0; nt < 4; nt++) {
                if (nt >= NT1) break;
                int tile = (wm * 2 + mt) * 16 + wn * NT1 + nt;
                float* tb = (float*)fragQ + tile * 128;
                tb[l0 * 4 + s0]     = tf32r(accA[mt][nt][0]);
                tb[l1 * 4 + s1]     = tf32r(accA[mt][nt][1]);
                tb[l0 * 4 + s0 + 1] = tf32r(accA[mt][nt][2]);
                tb[l1 * 4 + s1 + 1] = tf32r(accA[mt][nt][3]);
            }
    }
    for (int i = 0; i < NJT; i++) {   // V: NJT*8 tiles / 8 warps
        int tile = i * 8 + wid;
        int ks = tile >> 3, tn = tile & 7;
        const float* vp = vin + ((size_t)(b * NN + n0 + ks * 8 + tq)) * Dd
                        + h * DHd + tn * 8 + g;
        fragB1[tile * 32 + lane] = make_uint2(tf32u(vp[0]), tf32u(vp[4 * Dd]));
    }
    __syncthreads();

    // ---- Phase 3: out += tril(A) . V ----
#pragma unroll 2
    for (int ks = 0; ks < 16; ks++) {
        if (ks >= NJT) break;
        uint4 af[2];
#pragma unroll
        for (int mt = 0; mt < 2; mt++)
            af[mt] = fragQ[((wm * 2 + mt) * 16 + ks) * 32 + lane];
#pragma unroll
        for (int nt = 0; nt < 2; nt++) {
            uint2 bf = fragB1[(ks * 8 + wn * 2 + nt) * 32 + lane];
            mma16n8k8(acc2[0][nt], (const uint32_t*)&af[0], (const uint32_t*)&bf);
            mma16n8k8(acc2[1][nt], (const uint32_t*)&af[1], (const uint32_t*)&bf);
        }
    }

    // ---- Epilogue ----
#pragma unroll
    for (int mt = 0; mt < 2; mt++) {
        int i0 = wm * 32 + mt * 16 + g;
        float d0 = dinv[i0], d1 = dinv[i0 + 8];
        float* op0 = outp + ((size_t)(b * NN + n0 + r0c + i0)) * Dd + h * DHd;
        float* op1 = op0 + (size_t)8 * Dd;
#pragma unroll
        for (int nt = 0; nt < 2; nt++) {
            int e = (wn * 2 + nt) * 8 + tq * 2;
            *(float2*)(op0 + e) = make_float2(acc2[mt][nt][0] * d0,
                                              acc2[mt][nt][1] * d0);
            *(float2*)(op1 + e) = make_float2(acc2[mt][nt][2] * d1,
                                              acc2[mt][nt][3] * d1);
        }
    }
}

// ---------------------------------------------------------------------------
extern "C" void kernel_launch(void* const* d_in, const int* in_sizes, int n_in,
                              void* d_out, int out_size) {
    (void)in_sizes; (void)n_in; (void)out_size;
    const float* q    = (const float*)d_in[0];
    const float* k    = (const float*)d_in[1];
    const float* v    = (const float*)d_in[2];
    const float* proj = (const float*)d_in[3];
    float* out = (float*)d_out;

    cudaFuncSetAttribute(out_kernel, cudaFuncAttributeMaxDynamicSharedMemorySize,
                         OUT_DSMEM);

    feat_kernel<true><<<dim3(32, 32), 256>>>(q, proj);
    feat_kernel<false><<<dim3(32, 32), 256>>>(k, proj);
    chunk_kv_kernel<<<dim3(16, 32), 256>>>(v);
    prefix_kernel<<<2080, 256>>>();
    out_kernel<<<dim3(16, 32, 2), 256, OUT_DSMEM>>>(v, out);
}

// round 7
// speedup vs baseline: 1.1039x; 1.1039x over previous
#include <cuda_runtime.h>
#include <math.h>
#include <stdint.h>

// Problem constants
#define Bb 4
#define Hh 8
#define BHn 32
#define NN 2048
#define Dd 512
#define DHd 64
#define MF 256
#define CK 128
#define NC 16

// Scratch
__device__ float g_qp[(size_t)BHn * NN * MF];          // exp'd q features
__device__ float g_kp[(size_t)BHn * NN * MF];          // RAW dd - diag (exp at consumers)
__device__ float g_S [(size_t)BHn * NC * MF * DHd];
__device__ float g_z [BHn * NC * MF];
__device__ float g_kmax[BHn];

__device__ __forceinline__ float tf32r(float x) {
    uint32_t u = __float_as_uint(x);
    u = (u + 0x1000u) & 0xFFFFE000u;
    return __uint_as_float(u);
}
__device__ __forceinline__ uint32_t tf32u(float x) {
    return (__float_as_uint(x) + 0x1000u) & 0xFFFFE000u;
}
__device__ __forceinline__ float4 tf32v4(float4 v) {
    v.x = tf32r(v.x); v.y = tf32r(v.y); v.z = tf32r(v.z); v.w = tf32r(v.w);
    return v;
}
__device__ __forceinline__ float kfeat(float v, float m) {
    return 0.0625f * (__expf(v - m) + 1e-4f);
}
__device__ __forceinline__ float4 kfeat4(float4 v, float m) {
    v.x = kfeat(v.x, m); v.y = kfeat(v.y, m);
    v.z = kfeat(v.z, m); v.w = kfeat(v.w, m);
    return v;
}

// Warp-level tf32 MMA (portable ISA; tensor pipe)
__device__ __forceinline__ void mma16n8k8(float c[4], const uint32_t a[4],
                                          const uint32_t b[2]) {
    asm volatile(
        "mma.sync.aligned.m16n8k8.row.col.f32.tf32.tf32.f32 "
        "{%0,%1,%2,%3}, {%4,%5,%6,%7}, {%8,%9}, {%0,%1,%2,%3};"
        : "+f"(c[0]), "+f"(c[1]), "+f"(c[2]), "+f"(c[3])
        : "r"(a[0]), "r"(a[1]), "r"(a[2]), "r"(a[3]), "r"(b[0]), "r"(b[1]));
}

// ---------------------------------------------------------------------------
// Feature-map kernel (split-tf32 tensor core; __expf; inits g_kmax in Q pass)
// ---------------------------------------------------------------------------
template <bool IS_Q>
__global__ void __launch_bounds__(256) feat_kernel(const float* __restrict__ xin,
                                                   const float* __restrict__ proj) {
    __shared__ uint4 ps[1024];
    __shared__ float mx[64][2];
    __shared__ float bred[8];

    const int t = threadIdx.x, wid = t >> 5, lane = t & 31;
    const int g = lane >> 2, tq = lane & 3;
    const int wm = wid >> 1, wn = wid & 1;
    const int bh = blockIdx.y, b = bh >> 3, h = bh & 7;
    const int n0 = blockIdx.x * 64;
    const int r0 = n0 + wm * 16;

    if (IS_Q && blockIdx.x == 0 && t == 0) g_kmax[bh] = -1e30f;

    uint4 ah[8], al[8];
    float ss0 = 0.f, ss1 = 0.f;
    const float* xb = xin + ((size_t)b * NN + r0) * Dd + h * DHd;
#pragma unroll
    for (int ks = 0; ks < 8; ks++) {
        float x0 = xb[(size_t)g * Dd + ks * 8 + tq];
        float x1 = xb[(size_t)(g + 8) * Dd + ks * 8 + tq];
        float x2 = xb[(size_t)g * Dd + ks * 8 + tq + 4];
        float x3 = xb[(size_t)(g + 8) * Dd + ks * 8 + tq + 4];
        ss0 += x0 * x0 + x2 * x2;
        ss1 += x1 * x1 + x3 * x3;
        uint32_t h0 = __float_as_uint(x0) & 0xFFFFE000u;
        uint32_t h1 = __float_as_uint(x1) & 0xFFFFE000u;
        uint32_t h2 = __float_as_uint(x2) & 0xFFFFE000u;
        uint32_t h3 = __float_as_uint(x3) & 0xFFFFE000u;
        ah[ks] = make_uint4(h0, h1, h2, h3);
        al[ks] = make_uint4(__float_as_uint(x0 - __uint_as_float(h0)),
                            __float_as_uint(x1 - __uint_as_float(h1)),
                            __float_as_uint(x2 - __uint_as_float(h2)),
                            __float_as_uint(x3 - __uint_as_float(h3)));
    }
    ss0 += __shfl_xor_sync(0xffffffffu, ss0, 1);
    ss0 += __shfl_xor_sync(0xffffffffu, ss0, 2);
    ss1 += __shfl_xor_sync(0xffffffffu, ss1, 1);
    ss1 += __shfl_xor_sync(0xffffffffu, ss1, 2);
    const float diag0 = ss0 * 0.0625f, diag1 = ss1 * 0.0625f;

    float acc[16][4];
#pragma unroll
    for (int i = 0; i < 16; i++)
#pragma unroll
        for (int j = 0; j < 4; j++) acc[i][j] = 0.f;

    for (int ks = 0; ks < 8; ks++) {
        __syncthreads();
#pragma unroll
        for (int it = 0; it < 4; it++) {
            int slot = it * 256 + t;
            int nt = slot >> 5, sl = slot & 31;
            int sg = sl >> 2, stq = sl & 3;
            const float* pp = proj + (nt * 8 + sg) * 64 + ks * 8 + stq;
            float p0 = pp[0], p1 = pp[4];
            uint32_t h0 = __float_as_uint(p0) & 0xFFFFE000u;
            uint32_t h1 = __float_as_uint(p1) & 0xFFFFE000u;
            ps[slot] = make_uint4(h0, h1,
                                  __float_as_uint(p0 - __uint_as_float(h0)),
                                  __float_as_uint(p1 - __uint_as_float(h1)));
        }
        __syncthreads();
#pragma unroll
        for (int ntl = 0; ntl < 16; ntl++) {
            uint4 pv = ps[(wn * 16 + ntl) * 32 + lane];
            uint32_t bhi[2] = {pv.x, pv.y};
            uint32_t blo[2] = {pv.z, pv.w};
            mma16n8k8(acc[ntl], (const uint32_t*)&ah[ks], bhi);
            mma16n8k8(acc[ntl], (const uint32_t*)&al[ks], bhi);
            mma16n8k8(acc[ntl], (const uint32_t*)&ah[ks], blo);
        }
    }

    const float normalizer = 0.35355339059327373f;
#pragma unroll
    for (int ntl = 0; ntl < 16; ntl++)
#pragma unroll
        for (int j = 0; j < 4; j++) acc[ntl][j] *= normalizer;

    if (IS_Q) {
        float m0 = -1e30f, m1 = -1e30f;
#pragma unroll
        for (int ntl = 0; ntl < 16; ntl++) {
            m0 = fmaxf(m0, fmaxf(acc[ntl][0], acc[ntl][1]));
            m1 = fmaxf(m1, fmaxf(acc[ntl][2], acc[ntl][3]));
        }
        m0 = fmaxf(m0, __shfl_xor_sync(0xffffffffu, m0, 1));
        m0 = fmaxf(m0, __shfl_xor_sync(0xffffffffu, m0, 2));
        m1 = fmaxf(m1, __shfl_xor_sync(0xffffffffu, m1, 1));
        m1 = fmaxf(m1, __shfl_xor_sync(0xffffffffu, m1, 2));
        if (tq == 0) {
            mx[wm * 16 + g][wn] = m0;
            mx[wm * 16 + g + 8][wn] = m1;
        }
        __syncthreads();
        const float M0 = fmaxf(mx[wm * 16 + g][0], mx[wm * 16 + g][1]);
        const float M1 = fmaxf(mx[wm * 16 + g + 8][0], mx[wm * 16 + g + 8][1]);
        float* o0 = g_qp + ((size_t)bh * NN + r0 + g) * MF + wn * 128;
        float* o1 = g_qp + ((size_t)bh * NN + r0 + g + 8) * MF + wn * 128;
#pragma unroll
        for (int ntl = 0; ntl < 16; ntl++) {
            float2 v0, v1;
            v0.x = 0.0625f * (__expf(acc[ntl][0] - diag0 - M0) + 1e-4f);
            v0.y = 0.0625f * (__expf(acc[ntl][1] - diag0 - M0) + 1e-4f);
            v1.x = 0.0625f * (__expf(acc[ntl][2] - diag1 - M1) + 1e-4f);
            v1.y = 0.0625f * (__expf(acc[ntl][3] - diag1 - M1) + 1e-4f);
            *(float2*)(o0 + ntl * 8 + tq * 2) = v0;
            *(float2*)(o1 + ntl * 8 + tq * 2) = v1;
        }
    } else {
        float km = -1e30f;
        float* o0 = g_kp + ((size_t)bh * NN + r0 + g) * MF + wn * 128;
        float* o1 = g_kp + ((size_t)bh * NN + r0 + g + 8) * MF + wn * 128;
#pragma unroll
        for (int ntl = 0; ntl < 16; ntl++) {
            km = fmaxf(km, fmaxf(fmaxf(acc[ntl][0], acc[ntl][1]),
                                 fmaxf(acc[ntl][2], acc[ntl][3])));
            float2 v0 = make_float2(acc[ntl][0] - diag0, acc[ntl][1] - diag0);
            float2 v1 = make_float2(acc[ntl][2] - diag1, acc[ntl][3] - diag1);
            *(float2*)(o0 + ntl * 8 + tq * 2) = v0;
            *(float2*)(o1 + ntl * 8 + tq * 2) = v1;
        }
#pragma unroll
        for (int off = 16; off; off >>= 1)
            km = fmaxf(km, __shfl_xor_sync(0xffffffffu, km, off));
        if (lane == 0) bred[wid] = km;
        __syncthreads();
        if (t == 0) {
            float m = bred[0];
            for (int w = 1; w < 8; w++) m = fmaxf(m, bred[w]);
            int* addr = (int*)&g_kmax[bh];
            int old = *addr;
            while (__int_as_float(old) < m) {
                int assumed = old;
                old = atomicCAS(addr, assumed, __float_as_int(m));
                if (old == assumed) break;
            }
        }
    }
}

// ---------------------------------------------------------------------------
// Per-chunk local KV state; exp applied on the fly (g_kp holds raw dd-diag).
// ---------------------------------------------------------------------------
__global__ void __launch_bounds__(256) chunk_kv_kernel(const float* __restrict__ vin) {
    const int t = threadIdx.x, wid = t >> 5, lane = t & 31;
    const int g = lane >> 2, tq = lane & 3;
    const int c = blockIdx.x, bh = blockIdx.y;
    const int b = bh >> 3, h = bh & 7;
    const int n0 = c * CK;
    const float* kb = g_kp + (size_t)(bh * NN + n0) * MF;
    const float* vb = vin + ((size_t)(b * NN + n0)) * Dd + h * DHd;
    const float m = g_kmax[bh];

    float acc[2][8][4];
#pragma unroll
    for (int i = 0; i < 2; i++)
#pragma unroll
        for (int n = 0; n < 8; n++)
#pragma unroll
            for (int j = 0; j < 4; j++) acc[i][n][j] = 0.f;
    float z0[2] = {0.f, 0.f}, z1[2] = {0.f, 0.f};

    for (int tk = 0; tk < 16; tk++) {
        const int j0 = tk * 8 + tq, j1 = j0 + 4;
        uint32_t af[2][4];
#pragma unroll
        for (int i = 0; i < 2; i++) {
            int mm = (wid * 2 + i) * 16 + g;
            float a0 = kfeat(kb[(size_t)j0 * MF + mm], m);
            float a1 = kfeat(kb[(size_t)j0 * MF + mm + 8], m);
            float a2 = kfeat(kb[(size_t)j1 * MF + mm], m);
            float a3 = kfeat(kb[(size_t)j1 * MF + mm + 8], m);
            z0[i] += a0 + a2;
            z1[i] += a1 + a3;
            af[i][0] = tf32u(a0); af[i][1] = tf32u(a1);
            af[i][2] = tf32u(a2); af[i][3] = tf32u(a3);
        }
#pragma unroll
        for (int nt = 0; nt < 8; nt++) {
            uint32_t bf[2];
            bf[0] = tf32u(vb[(size_t)j0 * Dd + nt * 8 + g]);
            bf[1] = tf32u(vb[(size_t)j1 * Dd + nt * 8 + g]);
            mma16n8k8(acc[0][nt], af[0], bf);
            mma16n8k8(acc[1][nt], af[1], bf);
        }
    }

#pragma unroll
    for (int i = 0; i < 2; i++) {
        z0[i] += __shfl_xor_sync(0xffffffffu, z0[i], 1);
        z0[i] += __shfl_xor_sync(0xffffffffu, z0[i], 2);
        z1[i] += __shfl_xor_sync(0xffffffffu, z1[i], 1);
        z1[i] += __shfl_xor_sync(0xffffffffu, z1[i], 2);
    }
    if (tq == 0) {
        float* zp = g_z + (bh * NC + c) * MF;
#pragma unroll
        for (int i = 0; i < 2; i++) {
            int mm = (wid * 2 + i) * 16 + g;
            zp[mm] = z0[i];
            zp[mm + 8] = z1[i];
        }
    }

    float* Sp = g_S + (size_t)(bh * NC + c) * MF * DHd;
#pragma unroll
    for (int i = 0; i < 2; i++) {
        int mm = (wid * 2 + i) * 16 + g;
#pragma unroll
        for (int nt = 0; nt < 8; nt++) {
            *(float2*)(Sp + (size_t)mm * DHd + nt * 8 + tq * 2) =
                make_float2(acc[i][nt][0], acc[i][nt][1]);
            *(float2*)(Sp + (size_t)(mm + 8) * DHd + nt * 8 + tq * 2) =
                make_float2(acc[i][nt][2], acc[i][nt][3]);
        }
    }
}

// ---------------------------------------------------------------------------
// Fully parallel exclusive prefix
// ---------------------------------------------------------------------------
__global__ void __launch_bounds__(256) prefix_kernel() {
    const int blk = blockIdx.x;
    if (blk < 2048) {
        int idx = blk * 256 + threadIdx.x;
        int bh = idx >> 14;
        int me = idx & 16383;
        float* base = g_S + (size_t)bh * (NC * MF * DHd) + me;
        float run = 0.f;
#pragma unroll
        for (int c = 0; c < NC; c++) {
            float v = base[(size_t)c * (MF * DHd)];
            base[(size_t)c * (MF * DHd)] = run;
            run += v;
        }
    } else {
        int bh = blk - 2048;
        int mm = threadIdx.x;
        float* zb = g_z + bh * NC * MF + mm;
        float run = 0.f;
#pragma unroll
        for (int c = 0; c < NC; c++) {
            float v = zb[c * MF];
            zb[c * MF] = run;
            run += v;
        }
    }
}

// ---------------------------------------------------------------------------
// Output kernel: round-5 row-major/float4-staging version (proven fast),
// with exp applied elementwise to K tiles after the coalesced load.
// bufA: 64x132 row-major (Q half, later masked A).
// bufB0: <=128x68 (K tiles). bufB1: 128x72 (S halves / V).
// ---------------------------------------------------------------------------
#define PA 132
#define PB0 68
#define PB1 72
#define OFF_B0 8448
#define OFF_B1 (8448 + 8704)
#define OUT_DSMEM ((8448 + 8704 + 9216) * 4)

__global__ void __launch_bounds__(256, 2) out_kernel(const float* __restrict__ vin,
                                                     float* __restrict__ outp) {
    extern __shared__ float sm[];
    float* bufA = sm;
    float* bufB0 = sm + OFF_B0;
    float* bufB1 = sm + OFF_B1;
    __shared__ float den4[256];
    __shared__ float den[64];
    __shared__ float dinv[64];

    const int t = threadIdx.x, wid = t >> 5, lane = t & 31;
    const int g = lane >> 2, tq = lane & 3;
    const int wm = wid >> 2, wn = wid & 3;
    const int c = blockIdx.x, bh = blockIdx.y, hp = blockIdx.z;
    const int b = bh >> 3, h = bh & 7;
    const int n0 = c * CK;
    const int r0c = hp * 64;
    const int NT1 = hp ? 4 : 2;
    const int NJT = hp ? 16 : 8;

    const float* qbase = g_qp + (size_t)(bh * NN + n0 + r0c) * MF;
    const float* kbase = g_kp + (size_t)(bh * NN + n0) * MF;
    const float* Sbase = g_S + (size_t)(bh * NC + c) * MF * DHd;
    const float* zg = g_z + (bh * NC + c) * MF;
    const float kmaxv = g_kmax[bh];

    // den partial: q . (z_prev + 1e-6)
    {
        int i = t >> 2, qq = t & 3;
        float s = 0.f;
        const float* qr = qbase + (size_t)i * MF + qq * 64;
        const float* zr = zg + qq * 64;
#pragma unroll 4
        for (int mm = 0; mm < 64; mm += 4) {
            float4 q4 = *(const float4*)(qr + mm);
            s += q4.x * (zr[mm + 0] + 1e-6f) + q4.y * (zr[mm + 1] + 1e-6f)
               + q4.z * (zr[mm + 2] + 1e-6f) + q4.w * (zr[mm + 3] + 1e-6f);
        }
        den4[t] = s;
    }

    float accA[2][4][4];
#pragma unroll
    for (int i = 0; i < 2; i++)
#pragma unroll
        for (int j = 0; j < 4; j++)
#pragma unroll
            for (int s = 0; s < 4; s++) accA[i][j][s] = 0.f;
    float acc2[2][2][4];
#pragma unroll
    for (int i = 0; i < 2; i++)
#pragma unroll
        for (int j = 0; j < 2; j++)
#pragma unroll
            for (int s = 0; s < 4; s++) acc2[i][j][s] = 0.f;

    const int kIters = hp ? 8 : 4;

#pragma unroll 1
    for (int hf = 0; hf < 2; hf++) {
        if (hf) __syncthreads();
        // Stage Q half hf -> bufA (64 x 128), coalesced float4
#pragma unroll
        for (int it = 0; it < 8; it++) {
            int idx = it * 256 + t;
            int row = idx >> 5, c4 = idx & 31;
            float4 v = *(const float4*)(qbase + (size_t)row * MF + hf * 128 + c4 * 4);
            *(float4*)(bufA + row * PA + c4 * 4) = tf32v4(v);
        }
        // Stage K chunk kc=2*hf -> bufB0 (exp applied elementwise)
        for (int it = 0; it < kIters; it++) {
            int idx = it * 256 + t;
            int row = idx >> 4, c4 = idx & 15;
            float4 v = *(const float4*)(kbase + (size_t)row * MF + (2 * hf) * 64 + c4 * 4);
            *(float4*)(bufB0 + row * PB0 + c4 * 4) = tf32v4(kfeat4(v, kmaxv));
        }
        // Stage S half hf -> bufB1
#pragma unroll
        for (int it = 0; it < 8; it++) {
            int idx = it * 256 + t;
            int row = idx >> 4, c4 = idx & 15;
            float4 v = *(const float4*)(Sbase + (size_t)(hf * 128 + row) * DHd + c4 * 4);
            *(float4*)(bufB1 + row * PB1 + c4 * 4) = tf32v4(v);
        }
        __syncthreads();
        if (hf == 0 && t < 64)
            den[t] = den4[4 * t] + den4[4 * t + 1] + den4[4 * t + 2] + den4[4 * t + 3];

        // Phase 1 (kc = 2*hf): bufA cols 0..63
#pragma unroll
        for (int ks = 0; ks < 8; ks++) {
            uint32_t af[2][4];
#pragma unroll
            for (int mt = 0; mt < 2; mt++) {
                const float* ap = bufA + (wm * 32 + mt * 16 + g) * PA + ks * 8 + tq;
                af[mt][0] = __float_as_uint(ap[0]);
                af[mt][1] = __float_as_uint(ap[8 * PA]);
                af[mt][2] = __float_as_uint(ap[4]);
                af[mt][3] = __float_as_uint(ap[8 * PA + 4]);
            }
#pragma unroll
            for (int nt = 0; nt < 4; nt++) {
                if (nt >= NT1) break;
                const float* bp = bufB0 + ((wn * NT1 + nt) * 8 + g) * PB0 + ks * 8 + tq;
                uint32_t bf[2] = {__float_as_uint(bp[0]), __float_as_uint(bp[4])};
                mma16n8k8(accA[0][nt], af[0], bf);
                mma16n8k8(accA[1][nt], af[1], bf);
            }
        }
        // Phase 2 (S half hf): K = 128 over bufA cols 0..127
#pragma unroll 2
        for (int ks = 0; ks < 16; ks++) {
            uint32_t af[2][4];
#pragma unroll
            for (int mt = 0; mt < 2; mt++) {
                const float* ap = bufA + (wm * 32 + mt * 16 + g) * PA + ks * 8 + tq;
                af[mt][0] = __float_as_uint(ap[0]);
                af[mt][1] = __float_as_uint(ap[8 * PA]);
                af[mt][2] = __float_as_uint(ap[4]);
                af[mt][3] = __float_as_uint(ap[8 * PA + 4]);
            }
#pragma unroll
            for (int nt = 0; nt < 2; nt++) {
                const float* bp = bufB1 + (ks * 8 + tq) * PB1 + (wn * 2 + nt) * 8 + g;
                uint32_t bf[2] = {__float_as_uint(bp[0]), __float_as_uint(bp[4 * PB1])};
                mma16n8k8(acc2[0][nt], af[0], bf);
                mma16n8k8(acc2[1][nt], af[1], bf);
            }
        }
        __syncthreads();
        // Stage K chunk kc=2*hf+1 -> bufB0 (exp applied)
        for (int it = 0; it < kIters; it++) {
            int idx = it * 256 + t;
            int row = idx >> 4, c4 = idx & 15;
            float4 v = *(const float4*)(kbase + (size_t)row * MF + (2 * hf + 1) * 64 + c4 * 4);
            *(float4*)(bufB0 + row * PB0 + c4 * 4) = tf32v4(kfeat4(v, kmaxv));
        }
        __syncthreads();
        // Phase 1 (kc = 2*hf+1): bufA cols 64..127
#pragma unroll
        for (int ks = 0; ks < 8; ks++) {
            uint32_t af[2][4];
#pragma unroll
            for (int mt = 0; mt < 2; mt++) {
                const float* ap = bufA + (wm * 32 + mt * 16 + g) * PA + 64 + ks * 8 + tq;
                af[mt][0] = __float_as_uint(ap[0]);
                af[mt][1] = __float_as_uint(ap[8 * PA]);
                af[mt][2] = __float_as_uint(ap[4]);
                af[mt][3] = __float_as_uint(ap[8 * PA + 4]);
            }
#pragma unroll
            for (int nt = 0; nt < 4; nt++) {
                if (nt >= NT1) break;
                const float* bp = bufB0 + ((wn * NT1 + nt) * 8 + g) * PB0 + ks * 8 + tq;
                uint32_t bf[2] = {__float_as_uint(bp[0]), __float_as_uint(bp[4])};
                mma16n8k8(accA[0][nt], af[0], bf);
                mma16n8k8(accA[1][nt], af[1], bf);
            }
        }
    }

    // ---- Mask tril + rowsum -> den ----
#pragma unroll
    for (int mt = 0; mt < 2; mt++) {
        int i0 = wm * 32 + mt * 16 + g;
        int lim0 = r0c + i0, lim1 = lim0 + 8;
        float rs0 = 0.f, rs1 = 0.f;
#pragma unroll
        for (int nt = 0; nt < 4; nt++) {
            if (nt >= NT1) break;
            int cb = (wn * NT1 + nt) * 8 + tq * 2;
            float v0 = (cb     <= lim0) ? accA[mt][nt][0] : 0.f;
            float v1 = (cb + 1 <= lim0) ? accA[mt][nt][1] : 0.f;
            float v2 = (cb     <= lim1) ? accA[mt][nt][2] : 0.f;
            float v3 = (cb + 1 <= lim1) ? accA[mt][nt][3] : 0.f;
            accA[mt][nt][0] = v0; accA[mt][nt][1] = v1;
            accA[mt][nt][2] = v2; accA[mt][nt][3] = v3;
            rs0 += v0 + v1;
            rs1 += v2 + v3;
        }
        rs0 += __shfl_xor_sync(0xffffffffu, rs0, 1);
        rs0 += __shfl_xor_sync(0xffffffffu, rs0, 2);
        rs1 += __shfl_xor_sync(0xffffffffu, rs1, 1);
        rs1 += __shfl_xor_sync(0xffffffffu, rs1, 2);
        if (tq == 0) {
            atomicAdd(&den[i0], rs0);
            atomicAdd(&den[i0 + 8], rs1);
        }
    }
    __syncthreads();

    // ---- Store masked A into bufA row-major; stage V -> bufB1; dinv ----
    if (t < 64) dinv[t] = 1.0f / den[t];
#pragma unroll
    for (int mt = 0; mt < 2; mt++) {
        int i0 = wm * 32 + mt * 16 + g;
#pragma unroll
        for (int nt = 0; nt < 4; nt++) {
            if (nt >= NT1) break;
            int j = (wn * NT1 + nt) * 8 + tq * 2;
            *(float2*)(bufA + i0 * PA + j) =
                make_float2(tf32r(accA[mt][nt][0]), tf32r(accA[mt][nt][1]));
            *(float2*)(bufA + (i0 + 8) * PA + j) =
                make_float2(tf32r(accA[mt][nt][2]), tf32r(accA[mt][nt][3]));
        }
    }
    for (int it = 0; it < kIters; it++) {
        int idx = it * 256 + t;
        int row = idx >> 4, c4 = idx & 15;
        float4 v = *(const float4*)(vin + ((size_t)(b * NN + n0 + row)) * Dd
                                    + h * DHd + c4 * 4);
        *(float4*)(bufB1 + row * PB1 + c4 * 4) = tf32v4(v);
    }
    __syncthreads();

    // ---- Phase 3: out += tril(A) . V ----
#pragma unroll 2
    for (int ks = 0; ks < 16; ks++) {
        if (ks >= NJT) break;
        uint32_t af[2][4];
#pragma unroll
        for (int mt = 0; mt < 2; mt++) {
            const float* ap = bufA + (wm * 32 + mt * 16 + g) * PA + ks * 8 + tq;
            af[mt][0] = __float_as_uint(ap[0]);
            af[mt][1] = __float_as_uint(ap[8 * PA]);
            af[mt][2] = __float_as_uint(ap[4]);
            af[mt][3] = __float_as_uint(ap[8 * PA + 4]);
        }
#pragma unroll
        for (int nt = 0; nt < 2; nt++) {
            const float* bp = bufB1 + (ks * 8 + tq) * PB1 + (wn * 2 + nt) * 8 + g;
            uint32_t bf[2] = {__float_as_uint(bp[0]), __float_as_uint(bp[4 * PB1])};
            mma16n8k8(acc2[0][nt], af[0], bf);
            mma16n8k8(acc2[1][nt], af[1], bf);
        }
    }

    // ---- Epilogue ----
#pragma unroll
    for (int mt = 0; mt < 2; mt++) {
        int i0 = wm * 32 + mt * 16 + g;
        float d0 = dinv[i0], d1 = dinv[i0 + 8];
        float* op0 = outp + ((size_t)(b * NN + n0 + r0c + i0)) * Dd + h * DHd;
        float* op1 = op0 + (size_t)8 * Dd;
#pragma unroll
        for (int nt = 0; nt < 2; nt++) {
            int e = (wn * 2 + nt) * 8 + tq * 2;
            *(float2*)(op0 + e) = make_float2(acc2[mt][nt][0] * d0,
                                              acc2[mt][nt][1] * d0);
            *(float2*)(op1 + e) = make_float2(acc2[mt][nt][2] * d1,
                                              acc2[mt][nt][3] * d1);
        }
    }
}

// ---------------------------------------------------------------------------
extern "C" void kernel_launch(void* const* d_in, const int* in_sizes, int n_in,
                              void* d_out, int out_size) {
    (void)in_sizes; (void)n_in; (void)out_size;
    const float* q    = (const float*)d_in[0];
    const float* k    = (const float*)d_in[1];
    const float* v    = (const float*)d_in[2];
    const float* proj = (const float*)d_in[3];
    float* out = (float*)d_out;

    cudaFuncSetAttribute(out_kernel, cudaFuncAttributeMaxDynamicSharedMemorySize,
                         OUT_DSMEM);

    feat_kernel<true><<<dim3(32, 32), 256>>>(q, proj);
    feat_kernel<false><<<dim3(32, 32), 256>>>(k, proj);
    chunk_kv_kernel<<<dim3(16, 32), 256>>>(v);
    prefix_kernel<<<2080, 256>>>();
    out_kernel<<<dim3(16, 32, 2), 256, OUT_DSMEM>>>(v, out);
}